// round 13
// baseline (speedup 1.0000x reference)
#include <cuda_runtime.h>
#include <cuda_fp16.h>
#include <cstdint>

// out[i,j,o] = sum_h x[i+1,h]*x[j+1,h]*W[o,h] + b[o]
// (diff/W2 term is antisymmetric -> cancels under (P+P^T)/2 symmetrization)
//
// D_o = A_o B^T, A_o = X .* w_o, B = X (512x768 f32)
// fp32 approximated by ASYMMETRIC fp16 split: a*b ~= fp16(a)*(bhi+blo)
// (2 MMAs per k16 per channel; measured rel_err ~2e-4 < 1e-3).
//
// SINGLE fused kernel. Phase 1: cooperative LDG fp32 -> convert/split ->
// STS into a full-K resident smem image set (4 x 32x768 fp16, 194 KB).
// Phase 2: barrier-free LDSM+HMMA, 16 warps = 4 K-groups x 4 warps.
// Phase 3: smem combine + coalesced STG. Upper-tri 32x32 tiles + mirror.

#define HDIM 768
#define ROW_B 1552                 // 1536 B data + 16 B pad (388 w, mod32=4)
#define TILE_B (32 * ROW_B)        // 49664 B per image
#define NTILE 4                    // A0h A1h Bh Bl
#define SMEM_TOTAL (NTILE * TILE_B)   // 198656 B (1 CTA/SM)
#define FIN_STRIDE 66
#define FIN_B 8448                 // 32*66*4
#define PART_FLOATS 2048           // 32*32*2

union PackH8 { __half h[8]; uint4 v; };

__device__ __forceinline__ uint32_t smem_u32(const void* p) {
    uint32_t a;
    asm("{ .reg .u64 t; cvta.to.shared.u64 t, %1; cvt.u32.u64 %0, t; }"
        : "=r"(a) : "l"(p));
    return a;
}

__device__ __forceinline__ void sts16(uint32_t dst, uint4 v) {
    asm volatile("st.shared.v4.b32 [%0], {%1,%2,%3,%4};"
                 :: "r"(dst), "r"(v.x), "r"(v.y), "r"(v.z), "r"(v.w) : "memory");
}

__device__ __forceinline__ void ldsm4(uint32_t* r, uint32_t addr) {
    asm volatile("ldmatrix.sync.aligned.m8n8.x4.shared.b16 {%0,%1,%2,%3}, [%4];"
                 : "=r"(r[0]), "=r"(r[1]), "=r"(r[2]), "=r"(r[3]) : "r"(addr));
}

__device__ __forceinline__ void mmaf16(float* c, const uint32_t* a,
                                       uint32_t b0, uint32_t b1) {
    asm volatile(
        "mma.sync.aligned.m16n8k16.row.col.f32.f16.f16.f32 "
        "{%0,%1,%2,%3}, {%4,%5,%6,%7}, {%8,%9}, {%0,%1,%2,%3};"
        : "+f"(c[0]), "+f"(c[1]), "+f"(c[2]), "+f"(c[3])
        : "r"(a[0]), "r"(a[1]), "r"(a[2]), "r"(a[3]), "r"(b0), "r"(b1));
}

__global__ void __launch_bounds__(512, 1)
pairwise_fused_kernel(const float* __restrict__ x, const float* __restrict__ W,
                      const float* __restrict__ bias, float* __restrict__ out)
{
    // Triangular decode: blockIdx.x in [0,136) -> (bi, bj), bj >= bi
    int t = blockIdx.x;
    int bi = 0;
    while (t >= 16 - bi) { t -= 16 - bi; bi++; }
    const int bj = bi + t;

    extern __shared__ __align__(16) char smem[];
    const uint32_t sbase = smem_u32(smem);

    const int tid  = threadIdx.x;
    const int grp  = tid >> 7;        // K-group 0..3
    const int gtid = tid & 127;
    const int wid  = gtid >> 5;
    const int lane = tid & 31;
    const int wm = wid >> 1;          // warp row (0..1) of 16
    const int wn = wid & 1;           // warp col (0..1) of 16

    // ---- Phase 1: fused convert-load into resident smem images ----
    // 32 rows x 96 8-col chunks = 3072 chunks; 512 threads -> 6 each.
    {
        const float* xi = x + (size_t)(bi * 32) * HDIM;
        const float* xj = x + (size_t)(bj * 32) * HDIM;
        const float* w0 = W;
        const float* w1 = W + 1536;

#pragma unroll
        for (int p = 0; p < 6; p++) {
            const int c   = tid + p * 512;
            const int row = c / 96;
            const int k8  = (c % 96) * 8;
            const uint32_t so = sbase + (uint32_t)row * ROW_B + k8 * 2;

            float4 w0a = *(const float4*)(w0 + k8);
            float4 w0b = *(const float4*)(w0 + k8 + 4);
            float4 w1a = *(const float4*)(w1 + k8);
            float4 w1b = *(const float4*)(w1 + k8 + 4);
            float4 xa  = *(const float4*)(xi + (size_t)row * HDIM + k8);
            float4 xb  = *(const float4*)(xi + (size_t)row * HDIM + k8 + 4);
            float xs[8] = {xa.x, xa.y, xa.z, xa.w, xb.x, xb.y, xb.z, xb.w};
            float ws0[8] = {w0a.x, w0a.y, w0a.z, w0a.w, w0b.x, w0b.y, w0b.z, w0b.w};
            float ws1[8] = {w1a.x, w1a.y, w1a.z, w1a.w, w1b.x, w1b.y, w1b.z, w1b.w};

            PackH8 a0, a1;
#pragma unroll
            for (int u = 0; u < 8; u++) {
                a0.h[u] = __float2half_rn(xs[u] * ws0[u]);
                a1.h[u] = __float2half_rn(xs[u] * ws1[u]);
            }
            sts16(so + 0 * TILE_B, a0.v);
            sts16(so + 1 * TILE_B, a1.v);

            float4 ya = *(const float4*)(xj + (size_t)row * HDIM + k8);
            float4 yb = *(const float4*)(xj + (size_t)row * HDIM + k8 + 4);
            float ys[8] = {ya.x, ya.y, ya.z, ya.w, yb.x, yb.y, yb.z, yb.w};
            PackH8 bh, bl;
#pragma unroll
            for (int u = 0; u < 8; u++) {
                __half h = __float2half_rn(ys[u]);
                bh.h[u] = h;
                bl.h[u] = __float2half_rn(ys[u] - __half2float(h));
            }
            sts16(so + 2 * TILE_B, bh.v);
            sts16(so + 3 * TILE_B, bl.v);
        }
    }
    __syncthreads();

    // ---- Phase 2: barrier-free LDSM + HMMA over resident images ----
    // acc[ch][term][nf][4], term: 0 = A*Bhi, 1 = A*Blo
    float acc0[2][2][4] = {};
    float acc1[2][2][4] = {};

    const uint32_t arow = sbase + (uint32_t)(wm * 16 + (lane & 15)) * ROW_B
                        + ((lane >> 4) << 4);
    const uint32_t brow = sbase + (uint32_t)(wn * 16 + (lane & 15)) * ROW_B
                        + ((lane >> 4) << 4);
    const uint32_t kb = (uint32_t)(grp * 384);   // group K-range byte base

#pragma unroll
    for (int h = 0; h < 12; h++) {               // 12 k16 slices of K=192
        const uint32_t co = kb + h * 32;
        uint32_t a0[4], a1[4], bh[4], bl[4];
        ldsm4(a0, 0 * TILE_B + arow + co);
        ldsm4(a1, 1 * TILE_B + arow + co);
        ldsm4(bh, 2 * TILE_B + brow + co);
        ldsm4(bl, 3 * TILE_B + brow + co);
#pragma unroll
        for (int nf = 0; nf < 2; nf++) {
            mmaf16(acc0[0][nf], a0, bh[nf], bh[nf + 2]);
            mmaf16(acc1[0][nf], a1, bh[nf], bh[nf + 2]);
            mmaf16(acc0[1][nf], a0, bl[nf], bl[nf + 2]);
            mmaf16(acc1[1][nf], a1, bl[nf], bl[nf + 2]);
        }
    }

    // ---- Phase 3: combine 4 K-quarters via smem, then coalesced STG ----
    __syncthreads();
    float* fin  = (float*)smem;
    float* part = (float*)(smem + FIN_B);

    if (grp != 0) {
        float* pb = part + (grp - 1) * PART_FLOATS;
#pragma unroll
        for (int nf = 0; nf < 2; nf++)
#pragma unroll
            for (int r = 0; r < 4; r++) {
                const int idx = ((gtid * 2 + nf) * 4 + r) * 2;
                pb[idx + 0] = acc0[0][nf][r] + acc0[1][nf][r];
                pb[idx + 1] = acc1[0][nf][r] + acc1[1][nf][r];
            }
    }
    __syncthreads();

    if (grp == 0) {
        const float bv0 = bias[0];
        const float bv1 = bias[1];
#pragma unroll
        for (int nf = 0; nf < 2; nf++)
#pragma unroll
            for (int r = 0; r < 4; r++) {
                const int idx = ((gtid * 2 + nf) * 4 + r) * 2;
                const float v0 = acc0[0][nf][r] + acc0[1][nf][r]
                               + part[idx] + part[PART_FLOATS + idx]
                               + part[2 * PART_FLOATS + idx] + bv0;
                const float v1 = acc1[0][nf][r] + acc1[1][nf][r]
                               + part[idx + 1] + part[PART_FLOATS + idx + 1]
                               + part[2 * PART_FLOATS + idx + 1] + bv1;
                const int ii = wm * 16 + (lane >> 2) + ((r >> 1) << 3);
                const int jj = wn * 16 + nf * 8 + ((lane & 3) << 1) + (r & 1);
                fin[ii * FIN_STRIDE + jj * 2 + 0] = v0;
                fin[ii * FIN_STRIDE + jj * 2 + 1] = v1;
            }
    }
    __syncthreads();

    const int ib = bi * 32;
    const int jb = bj * 32;

    // Direct pass: 512 threads, each 2 cols of one row (contiguous float2)
    {
        const int ii = tid >> 4;
        const int j0 = (tid & 15) * 2;
        const int gi = ib + ii;
        if (gi >= 1 && gi <= 510) {
            float* orow = out + (size_t)(gi - 1) * 1020;
#pragma unroll
            for (int u = 0; u < 2; u++) {
                const int jj = j0 + u;
                const int gj = jb + jj;
                if (gj >= 1 && gj <= 510) {
                    float2 v = *(float2*)(fin + ii * FIN_STRIDE + jj * 2);
                    *(float2*)(orow + (size_t)(gj - 1) * 2) = v;
                }
            }
        }
    }
    // Mirror pass (off-diagonal tiles)
    if (bi != bj) {
        const int jj = tid >> 4;
        const int i0 = (tid & 15) * 2;
        const int gj = jb + jj;
        if (gj >= 1 && gj <= 510) {
            float* orow = out + (size_t)(gj - 1) * 1020;
#pragma unroll
            for (int u = 0; u < 2; u++) {
                const int ii = i0 + u;
                const int gi = ib + ii;
                if (gi >= 1 && gi <= 510) {
                    float2 v = *(float2*)(fin + ii * FIN_STRIDE + jj * 2);
                    *(float2*)(orow + (size_t)(gi - 1) * 2) = v;
                }
            }
        }
    }
}

// ---------------------------------------------------------------------------
extern "C" void kernel_launch(void* const* d_in, const int* in_sizes, int n_in,
                              void* d_out, int out_size)
{
    const float* x = (const float*)d_in[0];   // (1, 512, 768)
    const float* W = (const float*)d_in[1];   // (2, 1536)
    const float* b = (const float*)d_in[2];   // (2,)
    float* out = (float*)d_out;               // (510, 510, 2)

    cudaFuncSetAttribute(pairwise_fused_kernel,
                         cudaFuncAttributeMaxDynamicSharedMemorySize, SMEM_TOTAL);

    pairwise_fused_kernel<<<136, 512, SMEM_TOTAL>>>(x, W, b, out);
}